// round 2
// baseline (speedup 1.0000x reference)
#include <cuda_runtime.h>
#include <cstdint>

// ---------------------------------------------------------------------------
// HopfActivCpx: dz/dt = (a - b*|z|^2) * z, 50 DOPRI5 steps, t in [0, 2pi-2pi/unts]
// Elementwise over 2048x2048. Two elements per thread, packed into f32x2
// (Blackwell packed-fp32). Negation done via sign-bit XOR on the (idle) ALU
// pipe instead of an extra FFMA2, keeping the fma pipe for real work.
// ---------------------------------------------------------------------------

typedef unsigned long long u64;

__device__ __forceinline__ u64 pk(float lo, float hi) {
    u64 r;
    asm("mov.b64 %0, {%1, %2};" : "=l"(r) : "f"(lo), "f"(hi));
    return r;
}
__device__ __forceinline__ u64 pk2(float2 v) { return pk(v.x, v.y); }
__device__ __forceinline__ float2 up(u64 a) {
    float2 v;
    asm("mov.b64 {%0, %1}, %2;" : "=f"(v.x), "=f"(v.y) : "l"(a));
    return v;
}
__device__ __forceinline__ u64 f2fma(u64 a, u64 b, u64 c) {
    u64 d;
    asm("fma.rn.f32x2 %0, %1, %2, %3;" : "=l"(d) : "l"(a), "l"(b), "l"(c));
    return d;
}
__device__ __forceinline__ u64 f2mul(u64 a, u64 b) {
    u64 d;
    asm("mul.rn.f32x2 %0, %1, %2;" : "=l"(d) : "l"(a), "l"(b));
    return d;
}
// Negate both packed lanes: sign-bit XOR -> 2x LOP3 on the ALU pipe (free).
__device__ __forceinline__ u64 f2neg(u64 a) {
    return a ^ 0x8000000080000000ULL;
}

// Hopf RHS on a packed pair: f(z) = (a - b*(zr^2+zi^2)) * z.  NBr/NBi hold -b.
// 8 fma-pipe ops + 1 u64 XOR (alu pipe).
__device__ __forceinline__ void feval(u64 zr, u64 zi,
                                      u64 Ar, u64 Ai, u64 NBr, u64 NBi,
                                      u64& fr, u64& fi) {
    u64 s  = f2fma(zi, zi, f2mul(zr, zr));   // |z|^2
    u64 cr = f2fma(NBr, s, Ar);              // a_re - b_re*s
    u64 ci = f2fma(NBi, s, Ai);              // a_im - b_im*s
    u64 nq = f2neg(f2mul(ci, zi));           // -(ci*zi)   (XOR on alu pipe)
    fr = f2fma(cr, zr, nq);                  // cr*zr - ci*zi
    fi = f2fma(ci, zr, f2mul(cr, zi));       // cr*zi + ci*zr
}

__device__ __forceinline__ u64 hcoef(float h, double a) {
    float c = (float)a;      // coefficient rounded to f32 (as JAX weak-typing does)
    float v = h * c;         // fold h in once
    return pk(v, v);
}

__global__ void __launch_bounds__(256, 4)
hopf_dopri5_kernel(const float2* __restrict__ re_z, const float2* __restrict__ im_z,
                   const float2* __restrict__ re_a, const float2* __restrict__ im_a,
                   const float2* __restrict__ re_b, const float2* __restrict__ im_b,
                   const int*    __restrict__ unts,
                   float2* __restrict__ out, int npairs) {
    int i = blockIdx.x * blockDim.x + threadIdx.x;
    if (i >= npairs) return;

    // h = float32((2pi - 2pi/unts) / 50), computed in fp64 like the reference
    const double TWO_PI = 6.283185307179586476925286766559;
    double u = (double)unts[0];
    float h = (float)((TWO_PI - TWO_PI / u) / 50.0);

    // Butcher coefficients pre-multiplied by h, broadcast-packed (uniform)
    const u64 HA21 = hcoef(h, 1.0 / 5.0);
    const u64 HA31 = hcoef(h, 3.0 / 40.0);
    const u64 HA32 = hcoef(h, 9.0 / 40.0);
    const u64 HA41 = hcoef(h, 44.0 / 45.0);
    const u64 HA42 = hcoef(h, -56.0 / 15.0);
    const u64 HA43 = hcoef(h, 32.0 / 9.0);
    const u64 HA51 = hcoef(h, 19372.0 / 6561.0);
    const u64 HA52 = hcoef(h, -25360.0 / 2187.0);
    const u64 HA53 = hcoef(h, 64448.0 / 6561.0);
    const u64 HA54 = hcoef(h, -212.0 / 729.0);
    const u64 HA61 = hcoef(h, 9017.0 / 3168.0);
    const u64 HA62 = hcoef(h, -355.0 / 33.0);
    const u64 HA63 = hcoef(h, 46732.0 / 5247.0);
    const u64 HA64 = hcoef(h, 49.0 / 176.0);
    const u64 HA65 = hcoef(h, -5103.0 / 18656.0);
    const u64 HB1  = hcoef(h, 35.0 / 384.0);
    const u64 HB3  = hcoef(h, 500.0 / 1113.0);
    const u64 HB4  = hcoef(h, 125.0 / 192.0);
    const u64 HB5  = hcoef(h, -2187.0 / 6784.0);
    const u64 HB6  = hcoef(h, 11.0 / 84.0);

    // Load state + parameters (two adjacent elements per thread, LDG.64)
    u64 Zr = pk2(re_z[i]);
    u64 Zi = pk2(im_z[i]);
    u64 Ar = pk2(re_a[i]);
    u64 Ai = pk2(im_a[i]);
    float2 brv = re_b[i], biv = im_b[i];
    u64 NBr = pk(-brv.x, -brv.y);
    u64 NBi = pk(-biv.x, -biv.y);

    #pragma unroll 1
    for (int it = 0; it < 50; ++it) {
        u64 k1r, k1i, k2r, k2i, k3r, k3i, k4r, k4i, k5r, k5i, k6r, k6i;
        u64 zr, zi;

        feval(Zr, Zi, Ar, Ai, NBr, NBi, k1r, k1i);

        zr = f2fma(HA21, k1r, Zr);
        zi = f2fma(HA21, k1i, Zi);
        feval(zr, zi, Ar, Ai, NBr, NBi, k2r, k2i);

        zr = f2fma(HA31, k1r, Zr); zr = f2fma(HA32, k2r, zr);
        zi = f2fma(HA31, k1i, Zi); zi = f2fma(HA32, k2i, zi);
        feval(zr, zi, Ar, Ai, NBr, NBi, k3r, k3i);

        zr = f2fma(HA41, k1r, Zr); zr = f2fma(HA42, k2r, zr); zr = f2fma(HA43, k3r, zr);
        zi = f2fma(HA41, k1i, Zi); zi = f2fma(HA42, k2i, zi); zi = f2fma(HA43, k3i, zi);
        feval(zr, zi, Ar, Ai, NBr, NBi, k4r, k4i);

        zr = f2fma(HA51, k1r, Zr); zr = f2fma(HA52, k2r, zr);
        zr = f2fma(HA53, k3r, zr); zr = f2fma(HA54, k4r, zr);
        zi = f2fma(HA51, k1i, Zi); zi = f2fma(HA52, k2i, zi);
        zi = f2fma(HA53, k3i, zi); zi = f2fma(HA54, k4i, zi);
        feval(zr, zi, Ar, Ai, NBr, NBi, k5r, k5i);

        zr = f2fma(HA61, k1r, Zr); zr = f2fma(HA62, k2r, zr);
        zr = f2fma(HA63, k3r, zr); zr = f2fma(HA64, k4r, zr); zr = f2fma(HA65, k5r, zr);
        zi = f2fma(HA61, k1i, Zi); zi = f2fma(HA62, k2i, zi);
        zi = f2fma(HA63, k3i, zi); zi = f2fma(HA64, k4i, zi); zi = f2fma(HA65, k5i, zi);
        feval(zr, zi, Ar, Ai, NBr, NBi, k6r, k6i);

        Zr = f2fma(HB1, k1r, Zr); Zr = f2fma(HB3, k3r, Zr); Zr = f2fma(HB4, k4r, Zr);
        Zr = f2fma(HB5, k5r, Zr); Zr = f2fma(HB6, k6r, Zr);
        Zi = f2fma(HB1, k1i, Zi); Zi = f2fma(HB3, k3i, Zi); Zi = f2fma(HB4, k4i, Zi);
        Zi = f2fma(HB5, k5i, Zi); Zi = f2fma(HB6, k6i, Zi);
    }

    // Output: stacked [real (N), imag (N)]
    out[i]          = up(Zr);
    out[npairs + i] = up(Zi);
}

extern "C" void kernel_launch(void* const* d_in, const int* in_sizes, int n_in,
                              void* d_out, int out_size) {
    const float2* re_z = (const float2*)d_in[0];
    const float2* im_z = (const float2*)d_in[1];
    const float2* re_a = (const float2*)d_in[2];
    const float2* im_a = (const float2*)d_in[3];
    const float2* re_b = (const float2*)d_in[4];
    const float2* im_b = (const float2*)d_in[5];
    const int*    unts = (const int*)d_in[7];
    float2* out = (float2*)d_out;

    int n = in_sizes[0];          // 2048*2048 elements
    int npairs = n / 2;           // 2 elements per thread
    int threads = 256;
    int blocks = (npairs + threads - 1) / threads;
    hopf_dopri5_kernel<<<blocks, threads>>>(re_z, im_z, re_a, im_a, re_b, im_b,
                                            unts, out, npairs);
}

// round 3
// speedup vs baseline: 1.0519x; 1.0519x over previous
#include <cuda_runtime.h>
#include <cstdint>

// ---------------------------------------------------------------------------
// HopfActivCpx: dz/dt = (a - b*|z|^2) * z, 50 DOPRI5 steps.
// 4 elements per thread = 2 independent f32x2 (packed-fp32) groups, giving
// each warp 4 independent FFMA2 dependency chains to cover lat=4/rt=2 bubbles.
// B-weighted sum folded before the k6 feval to kill k1..k5 early (reg pressure).
// ---------------------------------------------------------------------------

typedef unsigned long long u64;

__device__ __forceinline__ u64 pk(float lo, float hi) {
    u64 r;
    asm("mov.b64 %0, {%1, %2};" : "=l"(r) : "f"(lo), "f"(hi));
    return r;
}
__device__ __forceinline__ float2 up(u64 a) {
    float2 v;
    asm("mov.b64 {%0, %1}, %2;" : "=f"(v.x), "=f"(v.y) : "l"(a));
    return v;
}
__device__ __forceinline__ u64 f2fma(u64 a, u64 b, u64 c) {
    u64 d;
    asm("fma.rn.f32x2 %0, %1, %2, %3;" : "=l"(d) : "l"(a), "l"(b), "l"(c));
    return d;
}
__device__ __forceinline__ u64 f2mul(u64 a, u64 b) {
    u64 d;
    asm("mul.rn.f32x2 %0, %1, %2;" : "=l"(d) : "l"(a), "l"(b));
    return d;
}

// Hopf RHS: f(z) = (a - b*|z|^2) * z.  NBr/NBi hold -b.  NEG1 = (-1,-1).
// 9 fma-pipe ops, depth 5, single pipe (no cross-pipe hops).
__device__ __forceinline__ void feval(u64 zr, u64 zi,
                                      u64 Ar, u64 Ai, u64 NBr, u64 NBi, u64 NEG1,
                                      u64& fr, u64& fi) {
    u64 s  = f2fma(zi, zi, f2mul(zr, zr));   // |z|^2
    u64 cr = f2fma(NBr, s, Ar);              // a_re - b_re*s
    u64 ci = f2fma(NBi, s, Ai);              // a_im - b_im*s
    u64 p  = f2mul(cr, zr);
    u64 q  = f2mul(ci, zi);
    fr = f2fma(q, NEG1, p);                  // cr*zr - ci*zi
    fi = f2fma(ci, zr, f2mul(cr, zi));       // cr*zi + ci*zr
}

__device__ __forceinline__ u64 hcoef(float h, double a) {
    float c = (float)a;      // coefficient rounded to f32 (JAX weak typing)
    float v = h * c;         // fold h in once
    return pk(v, v);
}

__global__ void __launch_bounds__(256, 2)
hopf_dopri5_kernel(const float4* __restrict__ re_z, const float4* __restrict__ im_z,
                   const float4* __restrict__ re_a, const float4* __restrict__ im_a,
                   const float4* __restrict__ re_b, const float4* __restrict__ im_b,
                   const int*    __restrict__ unts,
                   float4* __restrict__ out, int nquads) {
    int i = blockIdx.x * blockDim.x + threadIdx.x;
    if (i >= nquads) return;

    // h = float32((2pi - 2pi/unts) / 50), fp64 like the reference
    const double TWO_PI = 6.283185307179586476925286766559;
    double u = (double)unts[0];
    float h = (float)((TWO_PI - TWO_PI / u) / 50.0);

    const u64 HA21 = hcoef(h, 1.0 / 5.0);
    const u64 HA31 = hcoef(h, 3.0 / 40.0);
    const u64 HA32 = hcoef(h, 9.0 / 40.0);
    const u64 HA41 = hcoef(h, 44.0 / 45.0);
    const u64 HA42 = hcoef(h, -56.0 / 15.0);
    const u64 HA43 = hcoef(h, 32.0 / 9.0);
    const u64 HA51 = hcoef(h, 19372.0 / 6561.0);
    const u64 HA52 = hcoef(h, -25360.0 / 2187.0);
    const u64 HA53 = hcoef(h, 64448.0 / 6561.0);
    const u64 HA54 = hcoef(h, -212.0 / 729.0);
    const u64 HA61 = hcoef(h, 9017.0 / 3168.0);
    const u64 HA62 = hcoef(h, -355.0 / 33.0);
    const u64 HA63 = hcoef(h, 46732.0 / 5247.0);
    const u64 HA64 = hcoef(h, 49.0 / 176.0);
    const u64 HA65 = hcoef(h, -5103.0 / 18656.0);
    const u64 HB1  = hcoef(h, 35.0 / 384.0);
    const u64 HB3  = hcoef(h, 500.0 / 1113.0);
    const u64 HB4  = hcoef(h, 125.0 / 192.0);
    const u64 HB5  = hcoef(h, -2187.0 / 6784.0);
    const u64 HB6  = hcoef(h, 11.0 / 84.0);
    const u64 NEG1 = pk(-1.0f, -1.0f);

    // 2 packed groups: group 0 = elements 4i..4i+1, group 1 = 4i+2..4i+3
    float4 vzr = re_z[i], vzi = im_z[i];
    float4 var = re_a[i], vai = im_a[i];
    float4 vbr = re_b[i], vbi = im_b[i];

    u64 Zr[2]  = { pk(vzr.x, vzr.y), pk(vzr.z, vzr.w) };
    u64 Zi[2]  = { pk(vzi.x, vzi.y), pk(vzi.z, vzi.w) };
    u64 Ar[2]  = { pk(var.x, var.y), pk(var.z, var.w) };
    u64 Ai[2]  = { pk(vai.x, vai.y), pk(vai.z, vai.w) };
    u64 NBr[2] = { pk(-vbr.x, -vbr.y), pk(-vbr.z, -vbr.w) };
    u64 NBi[2] = { pk(-vbi.x, -vbi.y), pk(-vbi.z, -vbi.w) };

    #pragma unroll 1
    for (int it = 0; it < 50; ++it) {
        u64 k1r[2], k1i[2], k2r[2], k2i[2], k3r[2], k3i[2];
        u64 k4r[2], k4i[2], k5r[2], k5i[2], k6r[2], k6i[2];
        u64 zr[2], zi[2];

        #pragma unroll
        for (int g = 0; g < 2; ++g)
            feval(Zr[g], Zi[g], Ar[g], Ai[g], NBr[g], NBi[g], NEG1, k1r[g], k1i[g]);

        #pragma unroll
        for (int g = 0; g < 2; ++g) {
            zr[g] = f2fma(HA21, k1r[g], Zr[g]);
            zi[g] = f2fma(HA21, k1i[g], Zi[g]);
        }
        #pragma unroll
        for (int g = 0; g < 2; ++g)
            feval(zr[g], zi[g], Ar[g], Ai[g], NBr[g], NBi[g], NEG1, k2r[g], k2i[g]);

        #pragma unroll
        for (int g = 0; g < 2; ++g) {
            zr[g] = f2fma(HA31, k1r[g], Zr[g]); zr[g] = f2fma(HA32, k2r[g], zr[g]);
            zi[g] = f2fma(HA31, k1i[g], Zi[g]); zi[g] = f2fma(HA32, k2i[g], zi[g]);
        }
        #pragma unroll
        for (int g = 0; g < 2; ++g)
            feval(zr[g], zi[g], Ar[g], Ai[g], NBr[g], NBi[g], NEG1, k3r[g], k3i[g]);

        #pragma unroll
        for (int g = 0; g < 2; ++g) {
            zr[g] = f2fma(HA41, k1r[g], Zr[g]); zr[g] = f2fma(HA42, k2r[g], zr[g]);
            zr[g] = f2fma(HA43, k3r[g], zr[g]);
            zi[g] = f2fma(HA41, k1i[g], Zi[g]); zi[g] = f2fma(HA42, k2i[g], zi[g]);
            zi[g] = f2fma(HA43, k3i[g], zi[g]);
        }
        #pragma unroll
        for (int g = 0; g < 2; ++g)
            feval(zr[g], zi[g], Ar[g], Ai[g], NBr[g], NBi[g], NEG1, k4r[g], k4i[g]);

        #pragma unroll
        for (int g = 0; g < 2; ++g) {
            zr[g] = f2fma(HA51, k1r[g], Zr[g]); zr[g] = f2fma(HA52, k2r[g], zr[g]);
            zr[g] = f2fma(HA53, k3r[g], zr[g]); zr[g] = f2fma(HA54, k4r[g], zr[g]);
            zi[g] = f2fma(HA51, k1i[g], Zi[g]); zi[g] = f2fma(HA52, k2i[g], zi[g]);
            zi[g] = f2fma(HA53, k3i[g], zi[g]); zi[g] = f2fma(HA54, k4i[g], zi[g]);
        }
        #pragma unroll
        for (int g = 0; g < 2; ++g)
            feval(zr[g], zi[g], Ar[g], Ai[g], NBr[g], NBi[g], NEG1, k5r[g], k5i[g]);

        // stage-6 prep (last use of k2), then fold B-weighted k1,k3,k4,k5 into Z
        // BEFORE the k6 feval so k1..k5 die early (register pressure).
        #pragma unroll
        for (int g = 0; g < 2; ++g) {
            zr[g] = f2fma(HA61, k1r[g], Zr[g]); zr[g] = f2fma(HA62, k2r[g], zr[g]);
            zr[g] = f2fma(HA63, k3r[g], zr[g]); zr[g] = f2fma(HA64, k4r[g], zr[g]);
            zr[g] = f2fma(HA65, k5r[g], zr[g]);
            zi[g] = f2fma(HA61, k1i[g], Zi[g]); zi[g] = f2fma(HA62, k2i[g], zi[g]);
            zi[g] = f2fma(HA63, k3i[g], zi[g]); zi[g] = f2fma(HA64, k4i[g], zi[g]);
            zi[g] = f2fma(HA65, k5i[g], zi[g]);

            Zr[g] = f2fma(HB1, k1r[g], Zr[g]); Zr[g] = f2fma(HB3, k3r[g], Zr[g]);
            Zr[g] = f2fma(HB4, k4r[g], Zr[g]); Zr[g] = f2fma(HB5, k5r[g], Zr[g]);
            Zi[g] = f2fma(HB1, k1i[g], Zi[g]); Zi[g] = f2fma(HB3, k3i[g], Zi[g]);
            Zi[g] = f2fma(HB4, k4i[g], Zi[g]); Zi[g] = f2fma(HB5, k5i[g], Zi[g]);
        }
        #pragma unroll
        for (int g = 0; g < 2; ++g)
            feval(zr[g], zi[g], Ar[g], Ai[g], NBr[g], NBi[g], NEG1, k6r[g], k6i[g]);

        #pragma unroll
        for (int g = 0; g < 2; ++g) {
            Zr[g] = f2fma(HB6, k6r[g], Zr[g]);
            Zi[g] = f2fma(HB6, k6i[g], Zi[g]);
        }
    }

    // Output: stacked [real (N), imag (N)]
    float2 r0 = up(Zr[0]), r1 = up(Zr[1]);
    float2 i0 = up(Zi[0]), i1 = up(Zi[1]);
    out[i]          = make_float4(r0.x, r0.y, r1.x, r1.y);
    out[nquads + i] = make_float4(i0.x, i0.y, i1.x, i1.y);
}

extern "C" void kernel_launch(void* const* d_in, const int* in_sizes, int n_in,
                              void* d_out, int out_size) {
    const float4* re_z = (const float4*)d_in[0];
    const float4* im_z = (const float4*)d_in[1];
    const float4* re_a = (const float4*)d_in[2];
    const float4* im_a = (const float4*)d_in[3];
    const float4* re_b = (const float4*)d_in[4];
    const float4* im_b = (const float4*)d_in[5];
    const int*    unts = (const int*)d_in[7];
    float4* out = (float4*)d_out;

    int n = in_sizes[0];          // 2048*2048 elements
    int nquads = n / 4;           // 4 elements per thread
    int threads = 256;
    int blocks = (nquads + threads - 1) / threads;
    hopf_dopri5_kernel<<<blocks, threads>>>(re_z, im_z, re_a, im_a, re_b, im_b,
                                            unts, out, nquads);
}